// round 13
// baseline (speedup 1.0000x reference)
#include <cuda_runtime.h>
#include <cuda_bf16.h>
#include <cstdint>

// Problem: [8, 2048, 256] fp32 -> pairwise sq. distances [8, 2048, 2048]
#define BATCH 8
#define SEQ   2048
#define KDIM  256
#define BM    128                    // tile rows
#define BN    64                     // tile cols
#define NTJ   (SEQ / BN)             // 32 col-blocks
#define NPAIR 272                    // per batch: sum_{ti=0..15} (32 - 2*ti)
#define NWORK (NPAIR * BATCH)        // 2176
#define GRID_P 444                   // 148 SMs x 3 CTAs
#define BK    64                     // K halves per chunk (128B rows)
#define NCHUNK (KDIM / BK)           // 4

#define PITCH_H 72                   // halves per smem row (144B)
#define ROW_B   144
#define TILE_A_B (BM * ROW_B)        // 18432 B  (A: 128 rows)
#define TILE_B_B (BN * ROW_B)        // 9216 B   (B: 64 rows)
#define STAGE_B (TILE_A_B + TILE_B_B)   // 27648 B
#define SMEM_BYTES (2 * STAGE_B)     // 55296 B (2 stages; sd aliases them)
#define SD_PITCH 132                 // mirror staging pitch (floats)

__device__ float          g_norms[BATCH * SEQ];
__device__ __nv_bfloat16  g_xbf[BATCH * SEQ * KDIM];   // 8.4 MB bf16 copy

// ---------------------------------------------------------------------------
// PTX helpers (sm_80-era only: must compile for plain compute_100)
// ---------------------------------------------------------------------------
__device__ __forceinline__ uint32_t smem_u32(const void* p) {
    uint32_t a;
    asm("{ .reg .u64 t; cvta.to.shared.u64 t, %1; cvt.u32.u64 %0, t; }"
        : "=r"(a) : "l"(p));
    return a;
}
__device__ __forceinline__ void cp16(uint32_t dst, const void* src) {
    asm volatile("cp.async.cg.shared.global [%0], [%1], 16;"
                 :: "r"(dst), "l"(src) : "memory");
}
#define CP_COMMIT() asm volatile("cp.async.commit_group;" ::: "memory")
#define CP_WAIT(n)  asm volatile("cp.async.wait_group %0;" :: "n"(n) : "memory")

__device__ __forceinline__ void ldsm_x4(uint32_t addr, uint32_t* r) {
    asm volatile("ldmatrix.sync.aligned.m8n8.x4.shared.b16 {%0,%1,%2,%3}, [%4];"
                 : "=r"(r[0]), "=r"(r[1]), "=r"(r[2]), "=r"(r[3]) : "r"(addr));
}
__device__ __forceinline__ void mma_bf16(float* c, const uint32_t* a,
                                         const uint32_t* b) {
    asm volatile(
        "mma.sync.aligned.m16n8k16.row.col.f32.bf16.bf16.f32 "
        "{%0,%1,%2,%3}, {%4,%5,%6,%7}, {%8,%9}, {%0,%1,%2,%3};"
        : "+f"(c[0]), "+f"(c[1]), "+f"(c[2]), "+f"(c[3])
        : "r"(a[0]), "r"(a[1]), "r"(a[2]), "r"(a[3]), "r"(b[0]), "r"(b[1]));
}

// ---------------------------------------------------------------------------
// Kernel 1: per-row squared norms (fp32 exact) + bf16 conversion (RN)
// ---------------------------------------------------------------------------
__global__ void norms_conv_kernel(const float* __restrict__ x) {
    int row  = blockIdx.x * 8 + (threadIdx.x >> 5);
    int lane = threadIdx.x & 31;
    if (row >= BATCH * SEQ) return;
    const float4* p = (const float4*)(x + (size_t)row * KDIM);
    float4 v0 = p[2 * lane];
    float4 v1 = p[2 * lane + 1];
    float s = v0.x * v0.x + v0.y * v0.y + v0.z * v0.z + v0.w * v0.w +
              v1.x * v1.x + v1.y * v1.y + v1.z * v1.z + v1.w * v1.w;

    __nv_bfloat162 h[4];
    h[0] = __floats2bfloat162_rn(v0.x, v0.y);
    h[1] = __floats2bfloat162_rn(v0.z, v0.w);
    h[2] = __floats2bfloat162_rn(v1.x, v1.y);
    h[3] = __floats2bfloat162_rn(v1.z, v1.w);
    *(uint4*)(g_xbf + (size_t)row * KDIM + lane * 8) = *(const uint4*)h;

#pragma unroll
    for (int o = 16; o; o >>= 1) s += __shfl_xor_sync(0xffffffffu, s, o);
    if (lane == 0) g_norms[row] = s;
}

// decode work -> (b, ti [128-row block], tjh [64-col block])
__device__ __forceinline__ void decode_work(int work, int& b, int& ti, int& tjh) {
    b = work / NPAIR;
    int p = work % NPAIR;
    ti = 0;
    while (p >= NTJ - 2 * ti) { p -= NTJ - 2 * ti; ti++; }
    tjh = 2 * ti + p;
}

// ---------------------------------------------------------------------------
// Kernel 2: persistent bf16 mma.sync, 128x64 tiles, 3 CTAs/SM.
// Warp grid 4(M) x 2(N), warp tile 32x32. Diagonal-block halves are computed
// fully (no mirror); off-diagonal halves mirror via smem transpose staging
// that aliases the (dead) pipeline stages.
// ---------------------------------------------------------------------------
__global__ __launch_bounds__(256, 3)
void dist_mma(float* __restrict__ out) {
    extern __shared__ float smf[];
    __shared__ float s_ni[BM], s_nj[BN];
    const uint32_t smb = smem_u32(smf);

    const int tid  = threadIdx.x;
    const int lane = tid & 31;
    const int w    = tid >> 5;
    const int wm   = w & 3;          // warp row (4 x 32)
    const int wn   = w >> 2;         // warp col (2 x 32)
    const int gid  = lane >> 2;      // 0..7
    const int tig  = lane & 3;       // 0..3

    const uint32_t aoff = (uint32_t)(
        ((lane & 15) * PITCH_H + ((lane >> 4) & 1) * 8) * 2);
    const uint32_t boff4 = (uint32_t)(
        (((lane & 7) + 8 * ((lane >> 4) & 1)) * PITCH_H +
         ((lane >> 3) & 1) * 8) * 2);

    const int lrow = tid >> 3;       // loader: base row
    const int lg   = tid & 7;        // loader: 16B granule

    auto load_chunk = [&](const __nv_bfloat16* xb, int i0, int j0, int c, int s) {
        const uint32_t base = smb + (uint32_t)s * STAGE_B;
#pragma unroll
        for (int t = 0; t < 4; t++) {          // A: 128 rows
            const int row = lrow + t * 32;
            cp16(base + (uint32_t)(row * ROW_B + lg * 16),
                 xb + (size_t)(i0 + row) * KDIM + c * BK + lg * 8);
        }
#pragma unroll
        for (int t = 0; t < 2; t++) {          // B: 64 rows
            const int row = lrow + t * 32;
            cp16(base + TILE_A_B + (uint32_t)(row * ROW_B + lg * 16),
                 xb + (size_t)(j0 + row) * KDIM + c * BK + lg * 8);
        }
        CP_COMMIT();
    };

    for (int work = blockIdx.x; work < NWORK; work += GRID_P) {
        int b, ti, tjh;
        decode_work(work, b, ti, tjh);
        const int i0 = ti * BM, j0 = tjh * BN;
        const bool mirror = (tjh >= 2 * ti + 2);   // fully above diagonal block
        const __nv_bfloat16* xb = g_xbf + (size_t)b * SEQ * KDIM;
        float* ob = out + (size_t)b * SEQ * SEQ;

        load_chunk(xb, i0, j0, 0, 0);
        load_chunk(xb, i0, j0, 1, 1);
        if (tid < BM) s_ni[tid] = g_norms[b * SEQ + i0 + tid];
        else if (tid < BM + BN) s_nj[tid - BM] = g_norms[b * SEQ + j0 + tid - BM];

        float acc[2][4][4];
#pragma unroll
        for (int mt = 0; mt < 2; mt++)
#pragma unroll
            for (int nt = 0; nt < 4; nt++)
#pragma unroll
                for (int q = 0; q < 4; q++) acc[mt][nt][q] = 0.f;

        // ---------------- mainloop: 4 chunks, 2-stage pipeline -------------
        for (int c = 0; c < NCHUNK; c++) {
            if (c < NCHUNK - 1) { CP_WAIT(1); } else { CP_WAIT(0); }
            __syncthreads();

            const uint32_t As_u = smb +
                (uint32_t)((c & 1) * STAGE_B + wm * 32 * ROW_B) + aoff;
            const uint32_t Bs_u = smb +
                (uint32_t)((c & 1) * STAGE_B + TILE_A_B + wn * 32 * ROW_B) + boff4;

#pragma unroll
            for (int kk = 0; kk < 4; kk++) {
                uint32_t af[2][4], bf[4][2];
#pragma unroll
                for (int mt = 0; mt < 2; mt++)
                    ldsm_x4(As_u + (uint32_t)(mt * 16 * ROW_B + kk * 32), af[mt]);
#pragma unroll
                for (int nt = 0; nt < 4; nt += 2) {
                    uint32_t r4[4];
                    ldsm_x4(Bs_u + (uint32_t)(nt * 8 * ROW_B + kk * 32), r4);
                    bf[nt][0]     = r4[0];
                    bf[nt][1]     = r4[1];
                    bf[nt + 1][0] = r4[2];
                    bf[nt + 1][1] = r4[3];
                }
#pragma unroll
                for (int mt = 0; mt < 2; mt++)
#pragma unroll
                    for (int nt = 0; nt < 4; nt++)
                        mma_bf16(acc[mt][nt], af[mt], bf[nt]);
            }
            if (c + 2 < NCHUNK) {
                __syncthreads();
                load_chunk(xb, i0, j0, c + 2, c & 1);
            }
        }

        // ------- acc -> distances; zero exact diagonal ---------------------
#pragma unroll
        for (int mt = 0; mt < 2; mt++) {
            const int r0 = wm * 32 + mt * 16 + gid;
            const int r1 = r0 + 8;
            const float n0 = s_ni[r0], n1 = s_ni[r1];
#pragma unroll
            for (int nt = 0; nt < 4; nt++) {
                const int jc = wn * 32 + nt * 8 + tig * 2;
                const float m0 = s_nj[jc], m1 = s_nj[jc + 1];
                float d00 = fmaxf(n0 + m0 - 2.f * acc[mt][nt][0], 0.f);
                float d01 = fmaxf(n0 + m1 - 2.f * acc[mt][nt][1], 0.f);
                float d10 = fmaxf(n1 + m0 - 2.f * acc[mt][nt][2], 0.f);
                float d11 = fmaxf(n1 + m1 - 2.f * acc[mt][nt][3], 0.f);
                if (!mirror) {                 // tile may contain the diagonal
                    if (i0 + r0 == j0 + jc)     d00 = 0.f;
                    if (i0 + r0 == j0 + jc + 1) d01 = 0.f;
                    if (i0 + r1 == j0 + jc)     d10 = 0.f;
                    if (i0 + r1 == j0 + jc + 1) d11 = 0.f;
                }
                acc[mt][nt][0] = d00; acc[mt][nt][1] = d01;
                acc[mt][nt][2] = d10; acc[mt][nt][3] = d11;
            }
        }

        // ------- normal orientation: direct float2 stores ------------------
#pragma unroll
        for (int mt = 0; mt < 2; mt++) {
            const int r0 = wm * 32 + mt * 16 + gid;
#pragma unroll
            for (int nt = 0; nt < 4; nt++) {
                const int jc = wn * 32 + nt * 8 + tig * 2;
                *(float2*)(ob + (size_t)(i0 + r0) * SEQ + j0 + jc) =
                    make_float2(acc[mt][nt][0], acc[mt][nt][1]);
                *(float2*)(ob + (size_t)(i0 + r0 + 8) * SEQ + j0 + jc) =
                    make_float2(acc[mt][nt][2], acc[mt][nt][3]);
            }
        }

        // ------- mirror orientation (only fully-off-diagonal tiles) --------
        if (mirror) {
            float* sd = smf;                   // 64 x 132 fp32, aliases stages
            __syncthreads();                   // all stage ldsm reads done
#pragma unroll
            for (int mt = 0; mt < 2; mt++) {
                const int r0 = wm * 32 + mt * 16 + gid;
#pragma unroll
                for (int nt = 0; nt < 4; nt++) {
                    const int jc = wn * 32 + nt * 8 + tig * 2;
                    sd[jc * SD_PITCH + r0]           = acc[mt][nt][0];
                    sd[(jc + 1) * SD_PITCH + r0]     = acc[mt][nt][1];
                    sd[jc * SD_PITCH + r0 + 8]       = acc[mt][nt][2];
                    sd[(jc + 1) * SD_PITCH + r0 + 8] = acc[mt][nt][3];
                }
            }
            __syncthreads();
#pragma unroll
            for (int rr = 0; rr < 8; rr++) {
                const int jl = w * 8 + rr;     // 0..63 mirror row
                float4 v = *(const float4*)(sd + jl * SD_PITCH + lane * 4);
                *(float4*)(ob + (size_t)(j0 + jl) * SEQ + i0 + lane * 4) = v;
            }
        }

        __syncthreads();   // sd/norms reads done before next item's writes
    }
}

// ---------------------------------------------------------------------------
extern "C" void kernel_launch(void* const* d_in, const int* in_sizes, int n_in,
                              void* d_out, int out_size) {
    const float* x = (const float*)d_in[0];
    float* out = (float*)d_out;
    (void)in_sizes; (void)n_in; (void)out_size;

    cudaFuncSetAttribute(dist_mma, cudaFuncAttributeMaxDynamicSharedMemorySize,
                         SMEM_BYTES);
    norms_conv_kernel<<<(BATCH * SEQ + 7) / 8, 256>>>(x);
    dist_mma<<<GRID_P, 256, SMEM_BYTES>>>(out);
}

// round 14
// speedup vs baseline: 1.0333x; 1.0333x over previous
#include <cuda_runtime.h>
#include <cuda_bf16.h>
#include <cstdint>

// Problem: [8, 2048, 256] fp32 -> pairwise sq. distances [8, 2048, 2048]
#define BATCH 8
#define SEQ   2048
#define KDIM  256
#define BM    128
#define NT    (SEQ / BM)             // 16
#define NPAIR (NT * (NT + 1) / 2)    // 136 triangular tile pairs
#define NWORK (NPAIR * BATCH)        // 1088 work items
#define GRID_P 296                   // persistent: 148 SMs x 2 CTAs
#define BK    64                     // K halves per chunk (128B rows)
#define NCHUNK (KDIM / BK)           // 4

#define PITCH_H 72                           // halves per smem row (144B)
#define ROW_B   144                          // bytes per smem row
#define TILE_B  (BM * ROW_B)                 // 18432 B per tile
#define STAGE_B (2 * TILE_B)                 // A + B = 36864 B per stage
#define SD_OFF  (2 * STAGE_B)                // 73728: mirror staging buffer
#define SD_PITCH 132                         // floats
#define SMEM_BYTES (SD_OFF + 64 * SD_PITCH * 4)   // 107520 B

__device__ float          g_norms[BATCH * SEQ];
__device__ __nv_bfloat16  g_xbf[BATCH * SEQ * KDIM];   // 8.4 MB bf16 copy

// ---------------------------------------------------------------------------
// PTX helpers (sm_80-era only: must compile for plain compute_100)
// ---------------------------------------------------------------------------
__device__ __forceinline__ uint32_t smem_u32(const void* p) {
    uint32_t a;
    asm("{ .reg .u64 t; cvta.to.shared.u64 t, %1; cvt.u32.u64 %0, t; }"
        : "=r"(a) : "l"(p));
    return a;
}
__device__ __forceinline__ void cp16(uint32_t dst, const void* src) {
    asm volatile("cp.async.cg.shared.global [%0], [%1], 16;"
                 :: "r"(dst), "l"(src) : "memory");
}
#define CP_COMMIT() asm volatile("cp.async.commit_group;" ::: "memory")
#define CP_WAIT(n)  asm volatile("cp.async.wait_group %0;" :: "n"(n) : "memory")

__device__ __forceinline__ void ldsm_x4(uint32_t addr, uint32_t* r) {
    asm volatile("ldmatrix.sync.aligned.m8n8.x4.shared.b16 {%0,%1,%2,%3}, [%4];"
                 : "=r"(r[0]), "=r"(r[1]), "=r"(r[2]), "=r"(r[3]) : "r"(addr));
}
__device__ __forceinline__ void mma_bf16(float* c, const uint32_t* a,
                                         const uint32_t* b) {
    asm volatile(
        "mma.sync.aligned.m16n8k16.row.col.f32.bf16.bf16.f32 "
        "{%0,%1,%2,%3}, {%4,%5,%6,%7}, {%8,%9}, {%0,%1,%2,%3};"
        : "+f"(c[0]), "+f"(c[1]), "+f"(c[2]), "+f"(c[3])
        : "r"(a[0]), "r"(a[1]), "r"(a[2]), "r"(a[3]), "r"(b[0]), "r"(b[1]));
}
// streaming stores (evict-first): output is write-once, never re-read
__device__ __forceinline__ void stcs2(float* p, float a, float b) {
    asm volatile("st.global.cs.v2.f32 [%0], {%1, %2};" :: "l"(p), "f"(a), "f"(b)
                 : "memory");
}
__device__ __forceinline__ void stcs4(float* p, float4 v) {
    asm volatile("st.global.cs.v4.f32 [%0], {%1, %2, %3, %4};"
                 :: "l"(p), "f"(v.x), "f"(v.y), "f"(v.z), "f"(v.w) : "memory");
}

// ---------------------------------------------------------------------------
// Kernel 1: per-row squared norms (fp32 exact) + bf16 conversion (RN)
// ---------------------------------------------------------------------------
__global__ void norms_conv_kernel(const float* __restrict__ x) {
    int row  = blockIdx.x * 8 + (threadIdx.x >> 5);
    int lane = threadIdx.x & 31;
    if (row >= BATCH * SEQ) return;
    const float4* p = (const float4*)(x + (size_t)row * KDIM);
    float4 v0 = p[2 * lane];
    float4 v1 = p[2 * lane + 1];
    float s = v0.x * v0.x + v0.y * v0.y + v0.z * v0.z + v0.w * v0.w +
              v1.x * v1.x + v1.y * v1.y + v1.z * v1.z + v1.w * v1.w;

    __nv_bfloat162 h[4];
    h[0] = __floats2bfloat162_rn(v0.x, v0.y);
    h[1] = __floats2bfloat162_rn(v0.z, v0.w);
    h[2] = __floats2bfloat162_rn(v1.x, v1.y);
    h[3] = __floats2bfloat162_rn(v1.z, v1.w);
    *(uint4*)(g_xbf + (size_t)row * KDIM + lane * 8) = *(const uint4*)h;

#pragma unroll
    for (int o = 16; o; o >>= 1) s += __shfl_xor_sync(0xffffffffu, s, o);
    if (lane == 0) g_norms[row] = s;
}

__device__ __forceinline__ void decode_work(int work, int& b, int& ti, int& tj) {
    b = work / NPAIR;
    int p = work % NPAIR;
    ti = 0;
    while (p >= NT - ti) { p -= NT - ti; ti++; }
    tj = ti + p;
}

// ---------------------------------------------------------------------------
// Kernel 2: persistent bf16 mma.sync Gram + fp32 distance epilogue,
// cross-item cp.async prefetch; ALL output stores streaming (evict-first).
// ---------------------------------------------------------------------------
__global__ __launch_bounds__(256, 2)
void dist_mma(float* __restrict__ out) {
    extern __shared__ float smf[];
    __shared__ float s_ni[BM], s_nj[BM];
    const uint32_t smb = smem_u32(smf);

    const int tid  = threadIdx.x;
    const int lane = tid & 31;
    const int w    = tid >> 5;
    const int wm   = w & 1;          // warp row (2 x 64)
    const int wn   = w >> 1;         // warp col (4 x 32)
    const int gid  = lane >> 2;      // 0..7
    const int tig  = lane & 3;       // 0..3

    const uint32_t aoff = (uint32_t)(
        ((lane & 15) * PITCH_H + ((lane >> 4) & 1) * 8) * 2);
    const uint32_t boff4 = (uint32_t)(
        (((lane & 7) + 8 * ((lane >> 4) & 1)) * PITCH_H +
         ((lane >> 3) & 1) * 8) * 2);

    const int lrow = tid >> 3;
    const int lg   = tid & 7;

    auto load_chunk = [&](const __nv_bfloat16* xb, int i0, int j0, int c, int s) {
        const uint32_t base = smb + (uint32_t)s * STAGE_B;
#pragma unroll
        for (int t = 0; t < 4; t++) {
            const int row = lrow + t * 32;
            const uint32_t off = (uint32_t)(row * ROW_B + lg * 16);
            cp16(base + off,
                 xb + (size_t)(i0 + row) * KDIM + c * BK + lg * 8);
            cp16(base + TILE_B + off,
                 xb + (size_t)(j0 + row) * KDIM + c * BK + lg * 8);
        }
        CP_COMMIT();
    };

    int work = blockIdx.x;
    int b, ti, tj;
    if (work < NWORK) {
        decode_work(work, b, ti, tj);
        const __nv_bfloat16* xb = g_xbf + (size_t)b * SEQ * KDIM;
        load_chunk(xb, ti * BM, tj * BM, 0, 0);
        load_chunk(xb, ti * BM, tj * BM, 1, 1);
        if (tid < BM) s_ni[tid] = g_norms[b * SEQ + ti * BM + tid];
        else          s_nj[tid - BM] = g_norms[b * SEQ + tj * BM + tid - BM];
    }

    while (work < NWORK) {
        const int i0 = ti * BM, j0 = tj * BM;
        const bool diag = (ti == tj);
        const __nv_bfloat16* xb = g_xbf + (size_t)b * SEQ * KDIM;
        float* ob = out + (size_t)b * SEQ * SEQ;

        float acc[4][4][4];
#pragma unroll
        for (int mt = 0; mt < 4; mt++)
#pragma unroll
            for (int nt = 0; nt < 4; nt++)
#pragma unroll
                for (int q = 0; q < 4; q++) acc[mt][nt][q] = 0.f;

        for (int c = 0; c < NCHUNK; c++) {
            if (c < NCHUNK - 1) { CP_WAIT(1); } else { CP_WAIT(0); }
            __syncthreads();

            const uint32_t As_u = smb +
                (uint32_t)((c & 1) * STAGE_B + wm * 64 * ROW_B) + aoff;
            const uint32_t Bs_u = smb +
                (uint32_t)((c & 1) * STAGE_B + TILE_B + wn * 32 * ROW_B) + boff4;

#pragma unroll
            for (int kk = 0; kk < 4; kk++) {
                uint32_t af[4][4], bf[4][2];
#pragma unroll
                for (int mt = 0; mt < 4; mt++)
                    ldsm_x4(As_u + (uint32_t)(mt * 16 * ROW_B + kk * 32),
                            af[mt]);
#pragma unroll
                for (int nt = 0; nt < 4; nt += 2) {
                    uint32_t r4[4];
                    ldsm_x4(Bs_u + (uint32_t)(nt * 8 * ROW_B + kk * 32), r4);
                    bf[nt][0]     = r4[0];
                    bf[nt][1]     = r4[1];
                    bf[nt + 1][0] = r4[2];
                    bf[nt + 1][1] = r4[3];
                }
#pragma unroll
                for (int mt = 0; mt < 4; mt++)
#pragma unroll
                    for (int nt = 0; nt < 4; nt++)
                        mma_bf16(acc[mt][nt], af[mt], bf[nt]);
            }
            if (c + 2 < NCHUNK) {
                __syncthreads();
                load_chunk(xb, i0, j0, c + 2, c & 1);
            }
        }
        __syncthreads();

        // ------- acc -> distances (consumes s_ni/s_nj), diag zeroed --------
#pragma unroll
        for (int mt = 0; mt < 4; mt++) {
            const int r0 = wm * 64 + mt * 16 + gid;
            const int r1 = r0 + 8;
            const float n0 = s_ni[r0], n1 = s_ni[r1];
#pragma unroll
            for (int nt = 0; nt < 4; nt++) {
                const int jc = wn * 32 + nt * 8 + tig * 2;
                const float m0 = s_nj[jc], m1 = s_nj[jc + 1];
                float d00 = fmaxf(n0 + m0 - 2.f * acc[mt][nt][0], 0.f);
                float d01 = fmaxf(n0 + m1 - 2.f * acc[mt][nt][1], 0.f);
                float d10 = fmaxf(n1 + m0 - 2.f * acc[mt][nt][2], 0.f);
                float d11 = fmaxf(n1 + m1 - 2.f * acc[mt][nt][3], 0.f);
                if (diag) {
                    if (r0 == jc)     d00 = 0.f;
                    if (r0 == jc + 1) d01 = 0.f;
                    if (r1 == jc)     d10 = 0.f;
                    if (r1 == jc + 1) d11 = 0.f;
                }
                acc[mt][nt][0] = d00; acc[mt][nt][1] = d01;
                acc[mt][nt][2] = d10; acc[mt][nt][3] = d11;
            }
        }

        // ------- prefetch NEXT work item's chunk 0/1 into the stages -------
        const int nxt = work + GRID_P;
        int nb = 0, nti = 0, ntj = 0;
        if (nxt < NWORK) {
            decode_work(nxt, nb, nti, ntj);
            const __nv_bfloat16* nxb = g_xbf + (size_t)nb * SEQ * KDIM;
            load_chunk(nxb, nti * BM, ntj * BM, 0, 0);
            load_chunk(nxb, nti * BM, ntj * BM, 1, 1);
        }

        // ------- normal orientation: streaming float2 stores ---------------
#pragma unroll
        for (int mt = 0; mt < 4; mt++) {
            const int r0 = wm * 64 + mt * 16 + gid;
#pragma unroll
            for (int nt = 0; nt < 4; nt++) {
                const int jc = wn * 32 + nt * 8 + tig * 2;
                stcs2(ob + (size_t)(i0 + r0) * SEQ + j0 + jc,
                      acc[mt][nt][0], acc[mt][nt][1]);
                stcs2(ob + (size_t)(i0 + r0 + 8) * SEQ + j0 + jc,
                      acc[mt][nt][2], acc[mt][nt][3]);
            }
        }

        __syncthreads();   // all threads past s_ni/s_nj reads

        // ------- norms for next item (overlaps mirror epilogue) ------------
        if (nxt < NWORK) {
            if (tid < BM) s_ni[tid] = g_norms[nb * SEQ + nti * BM + tid];
            else          s_nj[tid - BM] = g_norms[nb * SEQ + ntj * BM + tid - BM];
        }

        // ------- mirror orientation: two 64-col half-passes via sd ---------
        if (!diag) {
            float* sd = smf + SD_OFF / 4;   // 64 x 132 floats
#pragma unroll
            for (int hh = 0; hh < 2; hh++) {
                if ((wn >> 1) == hh) {
#pragma unroll
                    for (int mt = 0; mt < 4; mt++) {
                        const int r0 = wm * 64 + mt * 16 + gid;
#pragma unroll
                        for (int nt = 0; nt < 4; nt++) {
                            const int jl = (wn & 1) * 32 + nt * 8 + tig * 2;
                            sd[jl * SD_PITCH + r0]           = acc[mt][nt][0];
                            sd[(jl + 1) * SD_PITCH + r0]     = acc[mt][nt][1];
                            sd[jl * SD_PITCH + r0 + 8]       = acc[mt][nt][2];
                            sd[(jl + 1) * SD_PITCH + r0 + 8] = acc[mt][nt][3];
                        }
                    }
                }
                __syncthreads();
#pragma unroll
                for (int rr = 0; rr < 8; rr++) {
                    const int jl = w * 8 + rr;
                    float4 v = *(const float4*)(sd + jl * SD_PITCH + lane * 4);
                    stcs4(ob + (size_t)(j0 + hh * 64 + jl) * SEQ + i0 + lane * 4,
                          v);
                }
                if (hh == 0) __syncthreads();
            }
        }

        work = nxt; b = nb; ti = nti; tj = ntj;
    }
}

// ---------------------------------------------------------------------------
extern "C" void kernel_launch(void* const* d_in, const int* in_sizes, int n_in,
                              void* d_out, int out_size) {
    const float* x = (const float*)d_in[0];
    float* out = (float*)d_out;
    (void)in_sizes; (void)n_in; (void)out_size;

    cudaFuncSetAttribute(dist_mma, cudaFuncAttributeMaxDynamicSharedMemorySize,
                         SMEM_BYTES);
    norms_conv_kernel<<<(BATCH * SEQ + 7) / 8, 256>>>(x);
    dist_mma<<<GRID_P, 256, SMEM_BYTES>>>(out);
}

// round 16
// speedup vs baseline: 1.0502x; 1.0164x over previous
#include <cuda_runtime.h>
#include <cuda_bf16.h>
#include <cstdint>

// Problem: [8, 2048, 256] fp32 -> pairwise sq. distances [8, 2048, 2048]
#define BATCH 8
#define SEQ   2048
#define KDIM  256
#define BM    128
#define NT    (SEQ / BM)             // 16
#define NPAIR (NT * (NT + 1) / 2)    // 136 triangular tile pairs
#define NWORK (NPAIR * BATCH)        // 1088 work items
#define GRID_P 296                   // persistent: 148 SMs x 2 CTAs
#define BK    64                     // K halves per chunk (128B rows)
#define NCHUNK (KDIM / BK)           // 4
#define THREADS 128                  // 4 warps, warp grid 2x2, warp tile 64x64

#define PITCH_H 72                           // halves per smem row (144B)
#define ROW_B   144                          // bytes per smem row
#define TILE_B  (BM * ROW_B)                 // 18432 B per tile
#define STAGE_B (2 * TILE_B)                 // A + B = 36864 B per stage
#define SD_OFF  (2 * STAGE_B)                // 73728: mirror staging buffer
#define SD_PITCH 132                         // floats
#define SMEM_BYTES (SD_OFF + 64 * SD_PITCH * 4)   // 107520 B

__device__ float          g_norms[BATCH * SEQ];
__device__ __nv_bfloat16  g_xbf[BATCH * SEQ * KDIM];   // 8.4 MB bf16 copy

// ---------------------------------------------------------------------------
// PTX helpers (sm_80-era only: must compile for plain compute_100)
// ---------------------------------------------------------------------------
__device__ __forceinline__ uint32_t smem_u32(const void* p) {
    uint32_t a;
    asm("{ .reg .u64 t; cvta.to.shared.u64 t, %1; cvt.u32.u64 %0, t; }"
        : "=r"(a) : "l"(p));
    return a;
}
__device__ __forceinline__ void cp16(uint32_t dst, const void* src) {
    asm volatile("cp.async.cg.shared.global [%0], [%1], 16;"
                 :: "r"(dst), "l"(src) : "memory");
}
#define CP_COMMIT() asm volatile("cp.async.commit_group;" ::: "memory")
#define CP_WAIT(n)  asm volatile("cp.async.wait_group %0;" :: "n"(n) : "memory")

__device__ __forceinline__ void ldsm_x4(uint32_t addr, uint32_t* r) {
    asm volatile("ldmatrix.sync.aligned.m8n8.x4.shared.b16 {%0,%1,%2,%3}, [%4];"
                 : "=r"(r[0]), "=r"(r[1]), "=r"(r[2]), "=r"(r[3]) : "r"(addr));
}
__device__ __forceinline__ void mma_bf16(float* c, const uint32_t* a,
                                         const uint32_t* b) {
    asm volatile(
        "mma.sync.aligned.m16n8k16.row.col.f32.bf16.bf16.f32 "
        "{%0,%1,%2,%3}, {%4,%5,%6,%7}, {%8,%9}, {%0,%1,%2,%3};"
        : "+f"(c[0]), "+f"(c[1]), "+f"(c[2]), "+f"(c[3])
        : "r"(a[0]), "r"(a[1]), "r"(a[2]), "r"(a[3]), "r"(b[0]), "r"(b[1]));
}
// streaming stores (evict-first): output is write-once, never re-read
__device__ __forceinline__ void stcs2(float* p, float a, float b) {
    asm volatile("st.global.cs.v2.f32 [%0], {%1, %2};" :: "l"(p), "f"(a), "f"(b)
                 : "memory");
}
__device__ __forceinline__ void stcs4(float* p, float4 v) {
    asm volatile("st.global.cs.v4.f32 [%0], {%1, %2, %3, %4};"
                 :: "l"(p), "f"(v.x), "f"(v.y), "f"(v.z), "f"(v.w) : "memory");
}

// ---------------------------------------------------------------------------
// Kernel 1: per-row squared norms (fp32 exact) + bf16 conversion (RN)
// ---------------------------------------------------------------------------
__global__ void norms_conv_kernel(const float* __restrict__ x) {
    int row  = blockIdx.x * 8 + (threadIdx.x >> 5);
    int lane = threadIdx.x & 31;
    if (row >= BATCH * SEQ) return;
    const float4* p = (const float4*)(x + (size_t)row * KDIM);
    float4 v0 = p[2 * lane];
    float4 v1 = p[2 * lane + 1];
    float s = v0.x * v0.x + v0.y * v0.y + v0.z * v0.z + v0.w * v0.w +
              v1.x * v1.x + v1.y * v1.y + v1.z * v1.z + v1.w * v1.w;

    __nv_bfloat162 h[4];
    h[0] = __floats2bfloat162_rn(v0.x, v0.y);
    h[1] = __floats2bfloat162_rn(v0.z, v0.w);
    h[2] = __floats2bfloat162_rn(v1.x, v1.y);
    h[3] = __floats2bfloat162_rn(v1.z, v1.w);
    *(uint4*)(g_xbf + (size_t)row * KDIM + lane * 8) = *(const uint4*)h;

#pragma unroll
    for (int o = 16; o; o >>= 1) s += __shfl_xor_sync(0xffffffffu, s, o);
    if (lane == 0) g_norms[row] = s;
}

__device__ __forceinline__ void decode_work(int work, int& b, int& ti, int& tj) {
    b = work / NPAIR;
    int p = work % NPAIR;
    ti = 0;
    while (p >= NT - ti) { p -= NT - ti; ti++; }
    tj = ti + p;
}

// ---------------------------------------------------------------------------
// Kernel 2: persistent bf16 mma.sync Gram, 4 warps, warp tile 64x64
// (high register reuse: 8 ldsm feed 32 MMAs per kk). Streaming stores.
// ---------------------------------------------------------------------------
__global__ __launch_bounds__(THREADS, 2)
void dist_mma(float* __restrict__ out) {
    extern __shared__ float smf[];
    __shared__ float s_ni[BM], s_nj[BM];
    const uint32_t smb = smem_u32(smf);

    const int tid  = threadIdx.x;
    const int lane = tid & 31;
    const int w    = tid >> 5;       // 0..3
    const int wm   = w & 1;          // warp row (2 x 64)
    const int wn   = w >> 1;         // warp col (2 x 64)
    const int gid  = lane >> 2;      // 0..7
    const int tig  = lane & 3;       // 0..3

    const uint32_t aoff = (uint32_t)(
        ((lane & 15) * PITCH_H + ((lane >> 4) & 1) * 8) * 2);
    const uint32_t boff4 = (uint32_t)(
        (((lane & 7) + 8 * ((lane >> 4) & 1)) * PITCH_H +
         ((lane >> 3) & 1) * 8) * 2);

    const int lrow = tid >> 3;       // 0..15
    const int lg   = tid & 7;

    auto load_chunk = [&](const __nv_bfloat16* xb, int i0, int j0, int c, int s) {
        const uint32_t base = smb + (uint32_t)s * STAGE_B;
#pragma unroll
        for (int t = 0; t < 8; t++) {
            const int row = lrow + t * 16;
            const uint32_t off = (uint32_t)(row * ROW_B + lg * 16);
            cp16(base + off,
                 xb + (size_t)(i0 + row) * KDIM + c * BK + lg * 8);
            cp16(base + TILE_B + off,
                 xb + (size_t)(j0 + row) * KDIM + c * BK + lg * 8);
        }
        CP_COMMIT();
    };

    int work = blockIdx.x;
    int b, ti, tj;
    if (work < NWORK) {
        decode_work(work, b, ti, tj);
        const __nv_bfloat16* xb = g_xbf + (size_t)b * SEQ * KDIM;
        load_chunk(xb, ti * BM, tj * BM, 0, 0);
        load_chunk(xb, ti * BM, tj * BM, 1, 1);
        s_ni[tid] = g_norms[b * SEQ + ti * BM + tid];
        s_nj[tid] = g_norms[b * SEQ + tj * BM + tid];
    }

    while (work < NWORK) {
        const int i0 = ti * BM, j0 = tj * BM;
        const bool diag = (ti == tj);
        const __nv_bfloat16* xb = g_xbf + (size_t)b * SEQ * KDIM;
        float* ob = out + (size_t)b * SEQ * SEQ;

        float acc[4][8][4];
#pragma unroll
        for (int mt = 0; mt < 4; mt++)
#pragma unroll
            for (int nt = 0; nt < 8; nt++)
#pragma unroll
                for (int q = 0; q < 4; q++) acc[mt][nt][q] = 0.f;

        for (int c = 0; c < NCHUNK; c++) {
            if (c < NCHUNK - 1) { CP_WAIT(1); } else { CP_WAIT(0); }
            __syncthreads();

            const uint32_t As_u = smb +
                (uint32_t)((c & 1) * STAGE_B + wm * 64 * ROW_B) + aoff;
            const uint32_t Bs_u = smb +
                (uint32_t)((c & 1) * STAGE_B + TILE_B + wn * 64 * ROW_B) + boff4;

#pragma unroll
            for (int kk = 0; kk < 4; kk++) {
                uint32_t af[4][4], bf[8][2];
#pragma unroll
                for (int mt = 0; mt < 4; mt++)
                    ldsm_x4(As_u + (uint32_t)(mt * 16 * ROW_B + kk * 32),
                            af[mt]);
#pragma unroll
                for (int nt = 0; nt < 8; nt += 2) {
                    uint32_t r4[4];
                    ldsm_x4(Bs_u + (uint32_t)(nt * 8 * ROW_B + kk * 32), r4);
                    bf[nt][0]     = r4[0];
                    bf[nt][1]     = r4[1];
                    bf[nt + 1][0] = r4[2];
                    bf[nt + 1][1] = r4[3];
                }
#pragma unroll
                for (int mt = 0; mt < 4; mt++)
#pragma unroll
                    for (int nt = 0; nt < 8; nt++)
                        mma_bf16(acc[mt][nt], af[mt], bf[nt]);
            }
            if (c + 2 < NCHUNK) {
                __syncthreads();
                load_chunk(xb, i0, j0, c + 2, c & 1);
            }
        }
        __syncthreads();

        // ------- acc -> distances (consumes s_ni/s_nj), diag zeroed --------
#pragma unroll
        for (int mt = 0; mt < 4; mt++) {
            const int r0 = wm * 64 + mt * 16 + gid;
            const int r1 = r0 + 8;
            const float n0 = s_ni[r0], n1 = s_ni[r1];
#pragma unroll
            for (int nt = 0; nt < 8; nt++) {
                const int jc = wn * 64 + nt * 8 + tig * 2;
                const float m0 = s_nj[jc], m1 = s_nj[jc + 1];
                float d00 = fmaxf(n0 + m0 - 2.f * acc[mt][nt][0], 0.f);
                float d01 = fmaxf(n0 + m1 - 2.f * acc[mt][nt][1], 0.f);
                float d10 = fmaxf(n1 + m0 - 2.f * acc[mt][nt][2], 0.f);
                float d11 = fmaxf(n1 + m1 - 2.f * acc[mt][nt][3], 0.f);
                if (diag) {
                    if (r0 == jc)     d00 = 0.f;
                    if (r0 == jc + 1) d01 = 0.f;
                    if (r1 == jc)     d10 = 0.f;
                    if (r1 == jc + 1) d11 = 0.f;
                }
                acc[mt][nt][0] = d00; acc[mt][nt][1] = d01;
                acc[mt][nt][2] = d10; acc[mt][nt][3] = d11;
            }
        }

        // ------- prefetch NEXT work item's chunk 0/1 into the stages -------
        const int nxt = work + GRID_P;
        int nb = 0, nti = 0, ntj = 0;
        if (nxt < NWORK) {
            decode_work(nxt, nb, nti, ntj);
            const __nv_bfloat16* nxb = g_xbf + (size_t)nb * SEQ * KDIM;
            load_chunk(nxb, nti * BM, ntj * BM, 0, 0);
            load_chunk(nxb, nti * BM, ntj * BM, 1, 1);
        }

        // ------- normal orientation: streaming float2 stores ---------------
#pragma unroll
        for (int mt = 0; mt < 4; mt++) {
            const int r0 = wm * 64 + mt * 16 + gid;
#pragma unroll
            for (int nt = 0; nt < 8; nt++) {
                const int jc = wn * 64 + nt * 8 + tig * 2;
                stcs2(ob + (size_t)(i0 + r0) * SEQ + j0 + jc,
                      acc[mt][nt][0], acc[mt][nt][1]);
                stcs2(ob + (size_t)(i0 + r0 + 8) * SEQ + j0 + jc,
                      acc[mt][nt][2], acc[mt][nt][3]);
            }
        }

        __syncthreads();   // all threads past s_ni/s_nj reads

        // ------- norms for next item ---------------------------------------
        if (nxt < NWORK) {
            s_ni[tid] = g_norms[nb * SEQ + nti * BM + tid];
            s_nj[tid] = g_norms[nb * SEQ + ntj * BM + tid];
        }

        // ------- mirror orientation: two 64-col half-passes via sd ---------
        if (!diag) {
            float* sd = smf + SD_OFF / 4;   // 64 x 132 floats
#pragma unroll
            for (int hh = 0; hh < 2; hh++) {
                if (wn == hh) {             // warps owning cols hh*64..
#pragma unroll
                    for (int mt = 0; mt < 4; mt++) {
                        const int r0 = wm * 64 + mt * 16 + gid;
#pragma unroll
                        for (int nt = 0; nt < 8; nt++) {
                            const int jl = nt * 8 + tig * 2;   // 0..63
                            sd[jl * SD_PITCH + r0]           = acc[mt][nt][0];
                            sd[(jl + 1) * SD_PITCH + r0]     = acc[mt][nt][1];
                            sd[jl * SD_PITCH + r0 + 8]       = acc[mt][nt][2];
                            sd[(jl + 1) * SD_PITCH + r0 + 8] = acc[mt][nt][3];
                        }
                    }
                }
                __syncthreads();
#pragma unroll
                for (int rr = 0; rr < 16; rr++) {
                    const int jl = w * 16 + rr;                // 0..63
                    float4 v = *(const float4*)(sd + jl * SD_PITCH + lane * 4);
                    stcs4(ob + (size_t)(j0 + hh * 64 + jl) * SEQ + i0 + lane * 4,
                          v);
                }
                if (hh == 0) __syncthreads();
            }
        }

        work = nxt; b = nb; ti = nti; tj = ntj;
    }
}

// ---------------------------------------------------------------------------
extern "C" void kernel_launch(void* const* d_in, const int* in_sizes, int n_in,
                              void* d_out, int out_size) {
    const float* x = (const float*)d_in[0];
    float* out = (float*)d_out;
    (void)in_sizes; (void)n_in; (void)out_size;

    cudaFuncSetAttribute(dist_mma, cudaFuncAttributeMaxDynamicSharedMemorySize,
                         SMEM_BYTES);
    norms_conv_kernel<<<(BATCH * SEQ + 7) / 8, 256>>>(x);
    dist_mma<<<GRID_P, THREADS, SMEM_BYTES>>>(out);
}